// round 11
// baseline (speedup 1.0000x reference)
#include <cuda_runtime.h>

#define NB 32
#define THREADS 768
#define NWARPS 24

// Cross-launch accumulators: zero at process start; the LAST block of every
// launch resets them after consuming, so graph replays are deterministic.
__device__ int g_hist[64];
__device__ unsigned int g_ctr = 0;

// Exact floor(clip(v)*32): saturate, FFMA.RZ with 2^23 (truncation == floor
// for non-negative), mask. NaN -> 0 (matches reference clip of -1 -> 0).
__device__ __forceinline__ int bin_uni(float v) {
    float t = __saturatef(v);
    float y = __fmaf_rz(t, 32.0f, 8388608.0f);   // 2^23
    int k = __float_as_int(y) & 63;              // 0..32
    return k > 31 ? 31 : k;
}
__device__ __forceinline__ int bin_gen(float v, const float* __restrict__ e) {
    int c = 0;
#pragma unroll
    for (int k = 0; k < 33; ++k) c += (v >= e[k]) ? 1 : 0;
    c -= 1;
    c = c < 0 ? 0 : c;
    return c > 31 ? 31 : c;
}

__device__ __forceinline__ float warp_sum(float v) {
#pragma unroll
    for (int off = 16; off > 0; off >>= 1)
        v += __shfl_xor_sync(0xffffffffu, v, off);
    return v;
}

// ---------------- generic fallback (correctness only, pure gmem) ----------------
__device__ void slow_loop(const float* __restrict__ x, float* __restrict__ out,
                          const float* __restrict__ W, const float* __restrict__ IW,
                          const float* __restrict__ bins,
                          const int* __restrict__ pair_i, const int* __restrict__ pair_j,
                          unsigned* __restrict__ myIdx, int* __restrict__ sHist,
                          int lane, int P, int gw, int nw, int B, float icpt, bool uni)
{
    const unsigned char* ib = (const unsigned char*)myIdx;
    const int fa = 4 * lane, fc = 128 + 4 * lane;
    int mpi = (lane < P) ? pair_i[lane] : 0;
    int mpj = (lane < P) ? pair_j[lane] : 0;
    for (int row = gw; row < B; row += nw) {
        const float4* rp = (const float4*)(x + (size_t)row * 256);
        float4 a = rp[lane], c = rp[32 + lane];
        float vv[8] = {a.x, a.y, a.z, a.w, c.x, c.y, c.z, c.w};
        int id[8];
#pragma unroll
        for (int j = 0; j < 8; ++j) {
            int f = (j < 4) ? fa + j : fc + (j - 4);
            id[j] = uni ? bin_uni(vv[j]) : bin_gen(vv[j], bins + f * 33);
        }
        float s = 0.f;
#pragma unroll
        for (int j = 0; j < 8; ++j) {
            int f = (j < 4) ? fa + j : fc + (j - 4);
            s += __ldg(&W[f * 32 + id[j]]);
        }
        myIdx[lane]      = (unsigned)id[0] | ((unsigned)id[1] << 8)
                         | ((unsigned)id[2] << 16) | ((unsigned)id[3] << 24);
        myIdx[32 + lane] = (unsigned)id[4] | ((unsigned)id[5] << 8)
                         | ((unsigned)id[6] << 16) | ((unsigned)id[7] << 24);
        __syncwarp();
        if (lane < P) s += __ldg(&IW[lane * 1024 + ib[mpi] * 32 + ib[mpj]]);
        if (lane == 0)      atomicAdd(&sHist[id[0]], 1);
        else if (lane == 1) atomicAdd(&sHist[32 + id[1]], 1);
        s = warp_sum(s);
        if (lane == 0) out[row] = icpt + s;
    }
}

__global__ __launch_bounds__(THREADS, 1)
void fair_ebm_kernel(const float* __restrict__ x, const float* __restrict__ W,
                     const float* __restrict__ IW, const float* __restrict__ intercept,
                     const float* __restrict__ bins, const int* __restrict__ pair_i,
                     const int* __restrict__ pair_j, float* __restrict__ out,
                     int B, int P, int writeLoss)
{
    extern __shared__ float smem[];
    float* sIW2  = smem;                     // 32*1024 folded: IW + W[2p][a] + W[2p+1][b]
    float* sWh   = sIW2 + 32768;             // W rows 64..255, stride 33 (192*33 = 6336)
    float* zeros = sWh + 6336;               // 32 zero floats (dummy-lookup target)
    float* sPart = zeros + 32;               // per-warp partials: NWARPS * 16 * 36
    int*   sHist = (int*)(sPart + NWARPS * 16 * 36);     // 64
    int*   sFlag = sHist + 64;                           // 2

    const int tid  = threadIdx.x;
    const int lane = tid & 31;
    const int warp = tid >> 5;
    const int TW   = gridDim.x * NWARPS;
    const int RPW  = (B + TW - 1) / TW;
    const int w    = blockIdx.x * NWARPS + warp;

    // ---- this warp's contiguous row range ----
    size_t row0 = (size_t)w * RPW;
    int nrt = 0;
    if (row0 < (size_t)B) {
        int rem = B - (int)row0;
        nrt = rem < RPW ? rem : RPW;
    }
    const int c3i = nrt - 1;                 // clamp index (valid when nrt > 0)
    const float4* xb = ((const float4*)x) + row0 * 64;

    // ---- ring preload (depth 4), issued BEFORE staging so DRAM ramps now ----
    float4 a0, c0, a1, c1, a2, c2, a3, c3;
    if (nrt > 0) {
        int r1 = 1 < c3i ? 1 : c3i;
        int r2 = 2 < c3i ? 2 : c3i;
        int r3 = 3 < c3i ? 3 : c3i;
        a0 = xb[lane];                 c0 = xb[32 + lane];
        a1 = xb[(size_t)r1 * 64 + lane]; c1 = xb[(size_t)r1 * 64 + 32 + lane];
        a2 = xb[(size_t)r2 * 64 + lane]; c2 = xb[(size_t)r2 * 64 + 32 + lane];
        a3 = xb[(size_t)r3 * 64 + lane]; c3 = xb[(size_t)r3 * 64 + 32 + lane];
    }

    if (tid == 0) { sFlag[0] = 1; sFlag[1] = 1; }
    if (tid < 64) sHist[tid] = 0;
    if (tid < 32) zeros[tid] = 0.0f;

    // ---- stage W rows 64..255 (bank-padded stride 33) ----
    {
        const float4* W4 = (const float4*)W;
        for (int i = tid; i < 1536; i += THREADS) {        // 192*32/4
            float4 v = W4[512 + i];                         // skip rows 0..63
            int f = i * 4;
            float* d = sWh + (f >> 5) * 33 + (f & 31);      // (f&31) <= 28
            d[0] = v.x; d[1] = v.y; d[2] = v.z; d[3] = v.w;
        }
    }
    // ---- verify uniform bins + identity pairs (P must be 32) ----
    {
        const float4* B4 = (const float4*)bins;
        bool bad = false;
        for (int i = tid; i < (256 * 33) / 4; i += THREADS) {
            float4 v = B4[i];
            int e = i * 4;
            bad |= (v.x != (float)((e + 0) % 33) * 0.03125f);
            bad |= (v.y != (float)((e + 1) % 33) * 0.03125f);
            bad |= (v.z != (float)((e + 2) % 33) * 0.03125f);
            bad |= (v.w != (float)((e + 3) % 33) * 0.03125f);
        }
        if (bad) sFlag[0] = 0;
    }
    if (tid == 0 && P != 32) sFlag[1] = 0;
    if (tid < 32 && tid < P) {
        if (pair_i[tid] != 2 * tid || pair_j[tid] != 2 * tid + 1) sFlag[1] = 0;
    }
    __syncthreads();

    const bool fast = (sFlag[0] != 0) && (sFlag[1] != 0);

    if (fast) {
        // fold: sIW2[p][a][b] = IW[p][a][b] + W[2p][a] + W[2p+1][b]
        const float4* IW4 = (const float4*)IW;
        float4* D4 = (float4*)sIW2;
        for (int i = tid; i < 8192; i += THREADS) {
            float4 v = IW4[i];
            int e = i * 4;
            int p = e >> 10, a = (e >> 5) & 31, b = e & 31;   // b multiple of 4
            float wa = __ldg(&W[(2 * p) * 32 + a]);
            float4 wb = __ldg((const float4*)&W[(2 * p + 1) * 32 + b]);
            v.x += wa + wb.x; v.y += wa + wb.y;
            v.z += wa + wb.z; v.w += wa + wb.w;
            D4[i] = v;
        }
    }
    __syncthreads();

    const float icpt = intercept[0];

    if (fast) {
        if (nrt > 0) {
            // per-lane loop-invariant lookup config (uniform, branch-free loop)
            const float *ub0, *ub1, *ub2, *ub3;
            int um, vm;
            if (lane < 16) {
                ub0 = sIW2 + (2 * lane) * 1024;       // T(2l)[a][b]
                ub1 = sIW2 + (2 * lane + 1) * 1024;   // T(2l+1)[a][b]
                ub2 = zeros; ub3 = zeros;
                um = 32; vm = 1;
            } else {
                int fr = 4 * lane - 64;               // sWh row of feature 4*lane
                ub0 = sWh + fr * 33;
                ub1 = sWh + (fr + 2) * 33;
                ub2 = sWh + (fr + 1) * 33;
                ub3 = sWh + (fr + 3) * 33;
                um = 1; vm = 0;
            }
            const float* hb = sWh + (64 + 4 * lane) * 33;   // feature 128+4*lane
            float* pbuf = sPart + warp * (16 * 36);

            int r = 0;

            // flush 16 (or count) accumulated rows: lane j sums row j's partials
#define FLUSH(BASEL, COUNT) do {                                              \
                __syncwarp();                                                 \
                if (lane < (COUNT)) {                                         \
                    const float4* rp_ = (const float4*)(pbuf + lane * 36);    \
                    float4 t0_ = rp_[0], t1_ = rp_[1], t2_ = rp_[2], t3_ = rp_[3]; \
                    float4 t4_ = rp_[4], t5_ = rp_[5], t6_ = rp_[6], t7_ = rp_[7]; \
                    float u0 = (t0_.x + t0_.y) + (t0_.z + t0_.w);             \
                    float u1 = (t1_.x + t1_.y) + (t1_.z + t1_.w);             \
                    float u2 = (t2_.x + t2_.y) + (t2_.z + t2_.w);             \
                    float u3 = (t3_.x + t3_.y) + (t3_.z + t3_.w);             \
                    float u4 = (t4_.x + t4_.y) + (t4_.z + t4_.w);             \
                    float u5 = (t5_.x + t5_.y) + (t5_.z + t5_.w);             \
                    float u6 = (t6_.x + t6_.y) + (t6_.z + t6_.w);             \
                    float u7 = (t7_.x + t7_.y) + (t7_.z + t7_.w);             \
                    float tot = ((u0 + u1) + (u2 + u3)) + ((u4 + u5) + (u6 + u7)); \
                    out[row0 + (BASEL) + lane] = icpt + tot;                  \
                }                                                             \
                __syncwarp();                                                 \
            } while (0)

            // process slot S, store partial, reload slot with row r+4 (clamped)
#define STEP(S) do {                                                          \
                int p0 = bin_uni(a##S.x), p1 = bin_uni(a##S.y);               \
                int p2 = bin_uni(a##S.z), p3 = bin_uni(a##S.w);               \
                int p4 = bin_uni(c##S.x), p5 = bin_uni(c##S.y);               \
                int p6 = bin_uni(c##S.z), p7 = bin_uni(c##S.w);               \
                float s = ub0[p0 * um + p1 * vm]                              \
                        + ub1[p2 * um + p3 * vm]                              \
                        + ub2[p1] + ub3[p3]                                   \
                        + hb[p4] + hb[33 + p5] + hb[66 + p6] + hb[99 + p7];   \
                if (lane == 0)      atomicAdd(&sHist[p0], 1);                 \
                else if (lane == 1) atomicAdd(&sHist[32 + p1], 1);            \
                pbuf[(r & 15) * 36 + lane] = s;                               \
                int rl_ = (r + 4) <= c3i ? (r + 4) : c3i;                     \
                const float4* xn_ = xb + (size_t)rl_ * 64;                    \
                a##S = xn_[lane]; c##S = xn_[32 + lane];                      \
                if ((r & 15) == 15) FLUSH(r - 15, 16);                        \
                ++r;                                                          \
            } while (0)

            const int nr4 = nrt & ~3;
            while (r < nr4) { STEP(0); STEP(1); STEP(2); STEP(3); }
            const int remn = nrt & 3;
            if (remn > 0) STEP(0);
            if (remn > 1) STEP(1);
            if (remn > 2) STEP(2);

            const int tb = nrt & ~15;
            const int tc = nrt - tb;
            if (tc) FLUSH(tb, tc);
#undef STEP
#undef FLUSH
        }
    } else {
        unsigned* myIdx = (unsigned*)(sPart + warp * (16 * 36));
        slow_loop(x, out, W, IW, bins, pair_i, pair_j, myIdx, sHist,
                  lane, P, w, TW, B, icpt, sFlag[0] != 0);
    }

    // ---- cross-block reduce + last-block finalize ----
    __syncthreads();
    if (tid < 64) atomicAdd(&g_hist[tid], sHist[tid]);
    __threadfence();
    __syncthreads();

    __shared__ unsigned ticket;
    if (tid == 0) ticket = atomicAdd(&g_ctr, 1u);
    __syncthreads();

    if (ticket == gridDim.x - 1) {
        if (tid < 64) sHist[tid] = atomicAdd(&g_hist[tid], 0);
        __syncthreads();
        if (tid < 32) {
            const double invB = 1.0 / (double)B;
            double vsum = 0.0;
#pragma unroll
            for (int s2i = 0; s2i < 2; ++s2i) {
                const int f = s2i ? 5 : 0;
                double wv  = (double)W[f * NB + tid];
                double cnt = (double)sHist[s2i * 32 + tid];
                double t1 = cnt * wv;
                double t2 = t1 * wv;
#pragma unroll
                for (int off = 16; off > 0; off >>= 1) {
                    t1 += __shfl_xor_sync(0xffffffffu, t1, off);
                    t2 += __shfl_xor_sync(0xffffffffu, t2, off);
                }
                double mean = t1 * invB;
                vsum += t2 * invB - mean * mean;
            }
            if (tid == 0) {
                if (writeLoss) out[B] = (float)(0.1 * vsum);
                g_ctr = 0;
            }
        }
        if (tid < 64) g_hist[tid] = 0;
        __threadfence();
    }
}

extern "C" void kernel_launch(void* const* d_in, const int* in_sizes, int n_in,
                              void* d_out, int out_size)
{
    const float* x         = (const float*)d_in[0];
    const float* W         = (const float*)d_in[1];
    const float* IW        = (const float*)d_in[2];
    const float* intercept = (const float*)d_in[3];
    const float* bins      = (const float*)d_in[4];
    const int*   pair_i    = (const int*)d_in[5];
    const int*   pair_j    = (const int*)d_in[6];
    float*       out       = (float*)d_out;

    const int B = in_sizes[0] / 256;
    const int P = in_sizes[2] / 1024;             // IW elements / (32*32)
    const int writeLoss = (out_size > B) ? 1 : 0;

    int dev = 0;
    cudaGetDevice(&dev);
    int sms = 148;
    cudaDeviceGetAttribute(&sms, cudaDevAttrMultiProcessorCount, dev);

    const size_t shbytes =
        (size_t)(32768 + 6336 + 32 + NWARPS * 16 * 36) * 4 + 64 * 4 + 32;
    cudaFuncSetAttribute(fair_ebm_kernel,
                         cudaFuncAttributeMaxDynamicSharedMemorySize, (int)shbytes);

    fair_ebm_kernel<<<sms, THREADS, shbytes>>>(x, W, IW, intercept, bins,
                                               pair_i, pair_j, out, B, P, writeLoss);
}